// round 7
// baseline (speedup 1.0000x reference)
#include <cuda_runtime.h>

#define N_NODES 4096
#define D_DIM   2048
#define B_SAMP  64

#define A_T_C    0.3f
#define DSBETA_C 1e-4f
#define E_B_C    0.5f
#define E_N_C    0.005f      // 0.01 * E_B
#define EPS_DS_C 0.01f

// Persistent state across the sequential scan (allocation-free scratch).
__device__ float g_M[(size_t)N_NODES * D_DIM];
__device__ float g_R[(size_t)N_NODES * D_DIM];
__device__ unsigned long long g_best[B_SAMP];
__device__ int g_nb_word32;   // 1 => neighbors stored as 32-bit words (int32/float32), 0 => bytes

__global__ void reset_best_kernel(const unsigned int* __restrict__ nb) {
    if (threadIdx.x < B_SAMP) g_best[threadIdx.x] = 0ULL;
    if (threadIdx.x == 0) {
        // Detect neighbor storage width. Bool widened to int32 -> words are 0/1.
        // Bool widened to float32 -> words are 0 / 0x3F800000. Raw 1-byte bools
        // -> random packed bytes; chance all 256 words land in the set is ~(1/8)^256.
        int w32 = 1;
        for (int i = 0; i < 256; i++) {
            unsigned v = nb[i];
            if (!(v == 0u || v == 1u || v == 0x3F800000u)) { w32 = 0; break; }
        }
        g_nb_word32 = w32;
    }
}

// Phase A: per-node activation + packed argmax via atomicMax.
// One block per node; 256 threads stream the D=2048 row as float4.
__global__ __launch_bounds__(256) void act_kernel(const float* __restrict__ x,
                                                  const float* __restrict__ W,
                                                  int t) {
    const int n   = blockIdx.x;
    const int tid = threadIdx.x;
    const float4* Wr = (const float4*)(W   + (size_t)n * D_DIM);
    const float4* Rr = (const float4*)(g_R + (size_t)n * D_DIM);
    const float4* xr = (const float4*)x;

    float dist = 0.f, rsum = 0.f;
#pragma unroll
    for (int k = 0; k < (D_DIM / 4) / 256; k++) {
        int i = k * 256 + tid;
        float4 w  = Wr[i];
        float4 r  = Rr[i];
        float4 xv = __ldg(&xr[i]);
        float d0 = xv.x - w.x, d1 = xv.y - w.y, d2 = xv.z - w.z, d3 = xv.w - w.w;
        dist += r.x * d0 * d0 + r.y * d1 * d1 + r.z * d2 * d2 + r.w * d3 * d3;
        rsum += r.x + r.y + r.z + r.w;
    }
#pragma unroll
    for (int o = 16; o > 0; o >>= 1) {
        dist += __shfl_down_sync(0xffffffffu, dist, o);
        rsum += __shfl_down_sync(0xffffffffu, rsum, o);
    }
    __shared__ float sd[8], sr[8];
    int wrp = tid >> 5, lane = tid & 31;
    if (lane == 0) { sd[wrp] = dist; sr[wrp] = rsum; }
    __syncthreads();
    if (tid == 0) {
        float dt = 0.f, rt = 0.f;
#pragma unroll
        for (int i = 0; i < 8; i++) { dt += sd[i]; rt += sr[i]; }
        float act = rt / (rt + dt + 1e-7f);
        // act > 0 always (R > 0) so the float bit pattern is order-preserving.
        // Low word = 0xFFFFFFFF - n so ties pick the SMALLEST node index
        // (matches jnp.argmax first-occurrence semantics).
        unsigned long long key =
            ((unsigned long long)__float_as_uint(act) << 32) |
            (unsigned long long)(0xFFFFFFFFu - (unsigned)n);
        atomicMax(&g_best[t], key);
    }
}

// Phase B: update winner + neighbors. One block per node; inactive blocks
// early-exit after one neighbor read.
__global__ __launch_bounds__(256) void update_kernel(const float* __restrict__ x,
                                                     float* __restrict__ W,
                                                     const void* __restrict__ nbv,
                                                     int t) {
    const unsigned long long key = g_best[t];
    const float act = __uint_as_float((unsigned)(key >> 32));
    if (!(act >= A_T_C)) return;  // do_upd == false -> whole step is a no-op
    const int winner = (int)(0xFFFFFFFFu - (unsigned)(key & 0xFFFFFFFFu));

    const int n = blockIdx.x;
    float lr;
    if (n == winner) {
        lr = E_B_C;
    } else {
        bool isnb;
        const size_t idx = (size_t)winner * N_NODES + n;
        if (g_nb_word32) {
            isnb = ((const unsigned int*)nbv)[idx] != 0u;
        } else {
            isnb = ((const unsigned char*)nbv)[idx] != 0;
        }
        if (!isnb) return;
        lr = E_N_C;
    }

    const int tid = threadIdx.x;
    float4* Wr = (float4*)(W   + (size_t)n * D_DIM);
    float4* Mr = (float4*)(g_M + (size_t)n * D_DIM);
    float4* Rr = (float4*)(g_R + (size_t)n * D_DIM);
    const float4* xr = (const float4*)x;

    const float c   = lr * DSBETA_C;
    const float omc = 1.0f - c;

    float4 Mn[2], Wn[2];
    float pmax = -1e30f, pmin = 1e30f, psum = 0.f;
#pragma unroll
    for (int k = 0; k < 2; k++) {
        int i = k * 256 + tid;
        float4 w  = Wr[i];
        float4 m  = Mr[i];
        float4 xv = __ldg(&xr[i]);
        float d0 = xv.x - w.x, d1 = xv.y - w.y, d2 = xv.z - w.z, d3 = xv.w - w.w;
        float4 mn;
        mn.x = c * fabsf(d0) + omc * m.x;
        mn.y = c * fabsf(d1) + omc * m.y;
        mn.z = c * fabsf(d2) + omc * m.z;
        mn.w = c * fabsf(d3) + omc * m.w;
        Mn[k] = mn;
        float4 wn;
        wn.x = w.x + lr * d0;
        wn.y = w.y + lr * d1;
        wn.z = w.z + lr * d2;
        wn.w = w.w + lr * d3;
        Wn[k] = wn;
        pmax = fmaxf(pmax, fmaxf(fmaxf(mn.x, mn.y), fmaxf(mn.z, mn.w)));
        pmin = fminf(pmin, fminf(fminf(mn.x, mn.y), fminf(mn.z, mn.w)));
        psum += mn.x + mn.y + mn.z + mn.w;
    }
    // 3-way block reduction (max, min, sum of M_new over the row)
#pragma unroll
    for (int o = 16; o > 0; o >>= 1) {
        pmax = fmaxf(pmax, __shfl_down_sync(0xffffffffu, pmax, o));
        pmin = fminf(pmin, __shfl_down_sync(0xffffffffu, pmin, o));
        psum +=            __shfl_down_sync(0xffffffffu, psum, o);
    }
    __shared__ float smax[8], smin[8], ssum[8];
    __shared__ float s_av, s_den;
    int wrp = tid >> 5, lane = tid & 31;
    if (lane == 0) { smax[wrp] = pmax; smin[wrp] = pmin; ssum[wrp] = psum; }
    __syncthreads();
    if (tid == 0) {
        float mx = -1e30f, mnv = 1e30f, sum = 0.f;
#pragma unroll
        for (int i = 0; i < 8; i++) {
            mx  = fmaxf(mx, smax[i]);
            mnv = fminf(mnv, smin[i]);
            sum += ssum[i];
        }
        s_av  = sum / (float)D_DIM;
        s_den = EPS_DS_C * (mx - mnv);
    }
    __syncthreads();
    const float av  = s_av;
    const float den = s_den;
    const bool  zero = (den == 0.0f);

#pragma unroll
    for (int k = 0; k < 2; k++) {
        int i = k * 256 + tid;
        float4 mn = Mn[k];
        float4 r;
        if (zero) {
            r.x = r.y = r.z = r.w = 1.0f;
        } else {
            float a0 = fminf(fmaxf((mn.x - av) / den, -80.0f), 80.0f);
            float a1 = fminf(fmaxf((mn.y - av) / den, -80.0f), 80.0f);
            float a2 = fminf(fmaxf((mn.z - av) / den, -80.0f), 80.0f);
            float a3 = fminf(fmaxf((mn.w - av) / den, -80.0f), 80.0f);
            r.x = 1.0f / (1.0f + expf(a0));
            r.y = 1.0f / (1.0f + expf(a1));
            r.z = 1.0f / (1.0f + expf(a2));
            r.w = 1.0f / (1.0f + expf(a3));
        }
        Mr[i] = mn;
        Rr[i] = r;
        Wr[i] = Wn[k];
    }
}

extern "C" void kernel_launch(void* const* d_in, const int* in_sizes, int n_in,
                              void* d_out, int out_size) {
    const float* x          = (const float*)d_in[0];   // [B, D]
    const float* weights    = (const float*)d_in[1];   // [N, D]
    const float* moving_avg = (const float*)d_in[2];   // [N, D]
    const float* relevances = (const float*)d_in[3];   // [N, D]
    // d_in[4] = wins (unused for output)
    const void*  neighbors  = d_in[5];                 // [N, N] bool (widened width auto-detected)

    float* W = (float*)d_out;

    void *pM = nullptr, *pR = nullptr;
    cudaGetSymbolAddress(&pM, g_M);
    cudaGetSymbolAddress(&pR, g_R);

    const size_t bytes = sizeof(float) * (size_t)N_NODES * D_DIM;
    cudaMemcpyAsync(W,  weights,    bytes, cudaMemcpyDeviceToDevice);
    cudaMemcpyAsync(pM, moving_avg, bytes, cudaMemcpyDeviceToDevice);
    cudaMemcpyAsync(pR, relevances, bytes, cudaMemcpyDeviceToDevice);

    reset_best_kernel<<<1, 64>>>((const unsigned int*)neighbors);

    for (int t = 0; t < B_SAMP; t++) {
        const float* xt = x + (size_t)t * D_DIM;
        act_kernel<<<N_NODES, 256>>>(xt, W, t);
        update_kernel<<<N_NODES, 256>>>(xt, W, neighbors, t);
    }
}